// round 1
// baseline (speedup 1.0000x reference)
#include <cuda_runtime.h>
#include <cstddef>

#define BB 2
#define SS 2048
#define DD 768
#define HH 12
#define DK 64
#define DFF 3072
#define MM (BB*SS)           // 4096
#define X2_ELEMS ((size_t)MM*DD)   // 3145728

// ---------------- scratch (static device globals; no allocation) -------------
__device__ float g_Q[(size_t)MM*DD];
__device__ float g_K[(size_t)MM*DD];
__device__ float g_V[(size_t)MM*DD];
__device__ float g_ctx[(size_t)MM*DD];
__device__ float g_x1[(size_t)MM*DD];
__device__ float g_t2[(size_t)MM*DD];      // attn_out, later ff2 (reused)
__device__ float g_ff[(size_t)MM*DFF];     // relu hidden

// ---------------- generic NN GEMM:  C = A[M,K] @ B[K,N] + bias, opt relu -----
// 64x64 tile, 16x16 threads, 4x4 per thread, BK=16
__global__ void sgemm_bias(const float* __restrict__ A, const float* __restrict__ B,
                           const float* __restrict__ bias, float* __restrict__ C,
                           int M, int N, int K, int relu)
{
    __shared__ float  As[16][65];
    __shared__ float4 Bs[16][16];
    int tx = threadIdx.x, ty = threadIdx.y;
    int tid = ty * 16 + tx;
    int row0 = blockIdx.y * 64, col0 = blockIdx.x * 64;

    int am = tid >> 2;            // 0..63
    int ak = (tid & 3) * 4;       // 0,4,8,12
    int bk = tid >> 4;            // 0..15
    int bn = tid & 15;            // float4 column

    float acc[4][4] = {};

    for (int k0 = 0; k0 < K; k0 += 16) {
        float4 av = *(const float4*)(A + (size_t)(row0 + am) * K + k0 + ak);
        As[ak + 0][am] = av.x; As[ak + 1][am] = av.y;
        As[ak + 2][am] = av.z; As[ak + 3][am] = av.w;
        Bs[bk][bn] = *(const float4*)(B + (size_t)(k0 + bk) * N + col0 + bn * 4);
        __syncthreads();
#pragma unroll
        for (int kk = 0; kk < 16; kk++) {
            float a0 = As[kk][ty * 4 + 0];
            float a1 = As[kk][ty * 4 + 1];
            float a2 = As[kk][ty * 4 + 2];
            float a3 = As[kk][ty * 4 + 3];
            float4 b = Bs[kk][tx];
            acc[0][0] += a0 * b.x; acc[0][1] += a0 * b.y; acc[0][2] += a0 * b.z; acc[0][3] += a0 * b.w;
            acc[1][0] += a1 * b.x; acc[1][1] += a1 * b.y; acc[1][2] += a1 * b.z; acc[1][3] += a1 * b.w;
            acc[2][0] += a2 * b.x; acc[2][1] += a2 * b.y; acc[2][2] += a2 * b.z; acc[2][3] += a2 * b.w;
            acc[3][0] += a3 * b.x; acc[3][1] += a3 * b.y; acc[3][2] += a3 * b.z; acc[3][3] += a3 * b.w;
        }
        __syncthreads();
    }

    float4 bv = *(const float4*)(bias + col0 + tx * 4);
#pragma unroll
    for (int i = 0; i < 4; i++) {
        float4 c;
        c.x = acc[i][0] + bv.x; c.y = acc[i][1] + bv.y;
        c.z = acc[i][2] + bv.z; c.w = acc[i][3] + bv.w;
        if (relu) {
            c.x = fmaxf(c.x, 0.f); c.y = fmaxf(c.y, 0.f);
            c.z = fmaxf(c.z, 0.f); c.w = fmaxf(c.w, 0.f);
        }
        *(float4*)(C + (size_t)(row0 + ty * 4 + i) * N + col0 + tx * 4) = c;
    }
}

// ---------------- scores: attn[bh, q, k] = (Q_bh @ K_bh^T) / 8 ----------------
// per (b,h): A = Q rows stride DD (offset h*64), B = K rows (NT)
__global__ void scores_kernel(const float* __restrict__ Q, const float* __restrict__ Km,
                              float* __restrict__ attn)
{
    __shared__ float As[16][65];
    __shared__ float Bs[16][65];
    int tx = threadIdx.x, ty = threadIdx.y;
    int tid = ty * 16 + tx;
    int bh = blockIdx.z;
    int b = bh / HH, h = bh % HH;
    size_t base = (size_t)b * SS * DD + (size_t)h * DK;
    int row0 = blockIdx.y * 64;   // q
    int col0 = blockIdx.x * 64;   // k

    int am = tid >> 2;
    int ak = (tid & 3) * 4;

    float acc[4][4] = {};

    for (int k0 = 0; k0 < DK; k0 += 16) {
        float4 av = *(const float4*)(Q  + base + (size_t)(row0 + am) * DD + k0 + ak);
        float4 bv = *(const float4*)(Km + base + (size_t)(col0 + am) * DD + k0 + ak);
        As[ak + 0][am] = av.x; As[ak + 1][am] = av.y; As[ak + 2][am] = av.z; As[ak + 3][am] = av.w;
        Bs[ak + 0][am] = bv.x; Bs[ak + 1][am] = bv.y; Bs[ak + 2][am] = bv.z; Bs[ak + 3][am] = bv.w;
        __syncthreads();
#pragma unroll
        for (int kk = 0; kk < 16; kk++) {
            float a[4], bb[4];
#pragma unroll
            for (int i = 0; i < 4; i++) a[i]  = As[kk][ty * 4 + i];
#pragma unroll
            for (int j = 0; j < 4; j++) bb[j] = Bs[kk][tx * 4 + j];
#pragma unroll
            for (int i = 0; i < 4; i++)
#pragma unroll
                for (int j = 0; j < 4; j++) acc[i][j] += a[i] * bb[j];
        }
        __syncthreads();
    }

    float* out = attn + (size_t)bh * SS * SS;
#pragma unroll
    for (int i = 0; i < 4; i++) {
        float4 c;
        c.x = acc[i][0] * 0.125f; c.y = acc[i][1] * 0.125f;
        c.z = acc[i][2] * 0.125f; c.w = acc[i][3] * 0.125f;
        *(float4*)(out + (size_t)(row0 + ty * 4 + i) * SS + col0 + tx * 4) = c;
    }
}

// ---------------- softmax, in place, one block per row ------------------------
__global__ void softmax_kernel(float* __restrict__ attn)
{
    size_t row = blockIdx.x;
    float* p = attn + row * SS;
    int t = threadIdx.x;     // 256 threads, 8 elems each
    __shared__ float red[256];

    float v[8];
    float m = -3.0e38f;
#pragma unroll
    for (int i = 0; i < 8; i++) { v[i] = p[t + i * 256]; m = fmaxf(m, v[i]); }
    red[t] = m; __syncthreads();
    for (int s = 128; s > 0; s >>= 1) { if (t < s) red[t] = fmaxf(red[t], red[t + s]); __syncthreads(); }
    m = red[0]; __syncthreads();

    float sum = 0.f;
#pragma unroll
    for (int i = 0; i < 8; i++) { v[i] = __expf(v[i] - m); sum += v[i]; }
    red[t] = sum; __syncthreads();
    for (int s = 128; s > 0; s >>= 1) { if (t < s) red[t] += red[t + s]; __syncthreads(); }
    float inv = 1.0f / red[0];
#pragma unroll
    for (int i = 0; i < 8; i++) p[t + i * 256] = v[i] * inv;
}

// ---------------- ctx: ctx[b,s,h,:] = attn_bh @ V_bh --------------------------
__global__ void ctx_kernel(const float* __restrict__ attn, const float* __restrict__ V,
                           float* __restrict__ ctx)
{
    __shared__ float  As[16][65];
    __shared__ float4 Bs[16][16];
    int tx = threadIdx.x, ty = threadIdx.y;
    int tid = ty * 16 + tx;
    int bh = blockIdx.z;
    int b = bh / HH, h = bh % HH;
    const float* Ab = attn + (size_t)bh * SS * SS;
    size_t vbase = (size_t)b * SS * DD + (size_t)h * DK;
    int row0 = blockIdx.y * 64;

    int am = tid >> 2;
    int ak = (tid & 3) * 4;
    int bk = tid >> 4;
    int bn = tid & 15;

    float acc[4][4] = {};

    for (int k0 = 0; k0 < SS; k0 += 16) {
        float4 av = *(const float4*)(Ab + (size_t)(row0 + am) * SS + k0 + ak);
        As[ak + 0][am] = av.x; As[ak + 1][am] = av.y; As[ak + 2][am] = av.z; As[ak + 3][am] = av.w;
        Bs[bk][bn] = *(const float4*)(V + vbase + (size_t)(k0 + bk) * DD + bn * 4);
        __syncthreads();
#pragma unroll
        for (int kk = 0; kk < 16; kk++) {
            float a0 = As[kk][ty * 4 + 0];
            float a1 = As[kk][ty * 4 + 1];
            float a2 = As[kk][ty * 4 + 2];
            float a3 = As[kk][ty * 4 + 3];
            float4 bq = Bs[kk][tx];
            acc[0][0] += a0 * bq.x; acc[0][1] += a0 * bq.y; acc[0][2] += a0 * bq.z; acc[0][3] += a0 * bq.w;
            acc[1][0] += a1 * bq.x; acc[1][1] += a1 * bq.y; acc[1][2] += a1 * bq.z; acc[1][3] += a1 * bq.w;
            acc[2][0] += a2 * bq.x; acc[2][1] += a2 * bq.y; acc[2][2] += a2 * bq.z; acc[2][3] += a2 * bq.w;
            acc[3][0] += a3 * bq.x; acc[3][1] += a3 * bq.y; acc[3][2] += a3 * bq.z; acc[3][3] += a3 * bq.w;
        }
        __syncthreads();
    }

#pragma unroll
    for (int i = 0; i < 4; i++) {
        float4 c = make_float4(acc[i][0], acc[i][1], acc[i][2], acc[i][3]);
        *(float4*)(ctx + vbase + (size_t)(row0 + ty * 4 + i) * DD + tx * 4) = c;
    }
}

// ---------------- residual + layernorm, one block per row ---------------------
__global__ void add_ln_kernel(const float* __restrict__ x, const float* __restrict__ y,
                              const float* __restrict__ g, const float* __restrict__ be,
                              float* __restrict__ out)
{
    size_t row = blockIdx.x;
    const float* px = x + row * DD;
    const float* py = y + row * DD;
    float* po = out + row * DD;
    int t = threadIdx.x;   // 256 threads, 3 elems each
    __shared__ float red[256];

    float a0 = px[t]       + py[t];
    float a1 = px[t + 256] + py[t + 256];
    float a2 = px[t + 512] + py[t + 512];

    red[t] = a0 + a1 + a2; __syncthreads();
    for (int s = 128; s > 0; s >>= 1) { if (t < s) red[t] += red[t + s]; __syncthreads(); }
    float mean = red[0] * (1.0f / DD); __syncthreads();

    float d0 = a0 - mean, d1 = a1 - mean, d2 = a2 - mean;
    red[t] = d0 * d0 + d1 * d1 + d2 * d2; __syncthreads();
    for (int s = 128; s > 0; s >>= 1) { if (t < s) red[t] += red[t + s]; __syncthreads(); }
    float rstd = rsqrtf(red[0] * (1.0f / DD) + 1e-5f);

    po[t]       = d0 * rstd * g[t]       + be[t];
    po[t + 256] = d1 * rstd * g[t + 256] + be[t + 256];
    po[t + 512] = d2 * rstd * g[t + 512] + be[t + 512];
}

// ---------------- launcher ----------------------------------------------------
extern "C" void kernel_launch(void* const* d_in, const int* in_sizes, int n_in,
                              void* d_out, int out_size)
{
    const float* x   = (const float*)d_in[0];
    const float* Wq  = (const float*)d_in[1];
    const float* bq  = (const float*)d_in[2];
    const float* Wk  = (const float*)d_in[3];
    const float* bk  = (const float*)d_in[4];
    const float* Wv  = (const float*)d_in[5];
    const float* bv  = (const float*)d_in[6];
    const float* Wo  = (const float*)d_in[7];
    const float* bo  = (const float*)d_in[8];
    const float* W1  = (const float*)d_in[9];
    const float* b1  = (const float*)d_in[10];
    const float* W2  = (const float*)d_in[11];
    const float* b2  = (const float*)d_in[12];
    const float* g1  = (const float*)d_in[13];
    const float* be1 = (const float*)d_in[14];
    const float* g2  = (const float*)d_in[15];
    const float* be2 = (const float*)d_in[16];

    float* out  = (float*)d_out;                 // x2: [2,2048,768]
    float* attn = out + X2_ELEMS;                // attn_weights: [2,12,2048,2048]

    float *Qp, *Kp, *Vp, *Cp, *X1p, *T2p, *FFp;
    cudaGetSymbolAddress((void**)&Qp,  g_Q);
    cudaGetSymbolAddress((void**)&Kp,  g_K);
    cudaGetSymbolAddress((void**)&Vp,  g_V);
    cudaGetSymbolAddress((void**)&Cp,  g_ctx);
    cudaGetSymbolAddress((void**)&X1p, g_x1);
    cudaGetSymbolAddress((void**)&T2p, g_t2);
    cudaGetSymbolAddress((void**)&FFp, g_ff);

    dim3 tb(16, 16);

    // Q, K, V projections
    sgemm_bias<<<dim3(DD / 64, MM / 64), tb>>>(x, Wq, bq, Qp, MM, DD, DD, 0);
    sgemm_bias<<<dim3(DD / 64, MM / 64), tb>>>(x, Wk, bk, Kp, MM, DD, DD, 0);
    sgemm_bias<<<dim3(DD / 64, MM / 64), tb>>>(x, Wv, bv, Vp, MM, DD, DD, 0);

    // scores directly into the output attn region, softmax in place
    scores_kernel<<<dim3(SS / 64, SS / 64, BB * HH), tb>>>(Qp, Kp, attn);
    softmax_kernel<<<BB * HH * SS, 256>>>(attn);

    // ctx = attn @ V (reads the final attn weights, never rewritten)
    ctx_kernel<<<dim3(1, SS / 64, BB * HH), tb>>>(attn, Vp, Cp);

    // attn_out = ctx @ Wo + bo
    sgemm_bias<<<dim3(DD / 64, MM / 64), tb>>>(Cp, Wo, bo, T2p, MM, DD, DD, 0);

    // x1 = LN(x + attn_out)
    add_ln_kernel<<<MM, 256>>>(x, T2p, g1, be1, X1p);

    // ff = relu(x1 @ W1 + b1); ff2 = ff @ W2 + b2
    sgemm_bias<<<dim3(DFF / 64, MM / 64), tb>>>(X1p, W1, b1, FFp, MM, DFF, DD, 1);
    sgemm_bias<<<dim3(DD / 64, MM / 64), tb>>>(FFp, W2, b2, T2p, MM, DD, DFF, 0);

    // x2 = LN(x1 + ff2) -> output
    add_ln_kernel<<<MM, 256>>>(X1p, T2p, g2, be2, out);
}

// round 2
// speedup vs baseline: 2.4762x; 2.4762x over previous
#include <cuda_runtime.h>
#include <cstdint>
#include <cstddef>

#define BB 2
#define SS 2048
#define DD 768
#define HH 12
#define DK 64
#define DFF 3072
#define MM (BB*SS)                 // 4096
#define X2_ELEMS ((size_t)MM*DD)   // 3145728

// ---------------- scratch (static device globals; no allocation) -------------
__device__ float g_Q[(size_t)MM*DD];
__device__ float g_K[(size_t)MM*DD];
__device__ float g_V[(size_t)MM*DD];
__device__ float g_ctx[(size_t)MM*DD];
__device__ float g_x1[(size_t)MM*DD];
__device__ float g_t2[(size_t)MM*DD];
__device__ float g_ff[(size_t)MM*DFF];

// ---------------- tf32 helpers ----------------------------------------------
__device__ __forceinline__ uint32_t f2tf(float f) {
    uint32_t u;
    asm("cvt.rna.tf32.f32 %0, %1;" : "=r"(u) : "f"(f));
    return u;
}

__device__ __forceinline__ void mma8(float* c, const uint32_t* a, const uint32_t* b) {
    asm volatile(
        "mma.sync.aligned.m16n8k8.row.col.f32.tf32.tf32.f32 "
        "{%0,%1,%2,%3},{%4,%5,%6,%7},{%8,%9},{%0,%1,%2,%3};\n"
        : "+f"(c[0]), "+f"(c[1]), "+f"(c[2]), "+f"(c[3])
        : "r"(a[0]), "r"(a[1]), "r"(a[2]), "r"(a[3]), "r"(b[0]), "r"(b[1]));
}

// ---------------- generic TF32 tensor-core GEMM ------------------------------
// C[M,N] = alpha * A @ op(B) + bias, optional relu.
// A: row-major m×k (lda). TB=false: B row-major k×n (ldb). TB=true: B row-major n×k (B^T used).
// Per-z offsets: off = (z/HH)*s1 + (z%HH)*s2 for each of A, B, C.
// Block tile BM×BN, BK=32, 256 threads (8 warps), warp tile WM×WN, mma m16n8k8.
template<int BM, int BN, int WM, int WN, bool TB>
__global__ void __launch_bounds__(256) gemm_tf32(
    const float* __restrict__ A, const float* __restrict__ B,
    const float* __restrict__ bias, float* __restrict__ C,
    int K, int lda, int ldb, int ldc,
    long long sA1, long long sA2, long long sB1, long long sB2,
    long long sC1, long long sC2, float alpha, int relu)
{
    constexpr int MI  = WM / 16;
    constexpr int NJ  = WN / 8;
    constexpr int WGN = BN / WN;
    constexpr int ASTR = 36;                    // [m][k] stride -> bank = (4m+k)%32
    constexpr int BSTR = TB ? 36 : (BN + 4);    // TB: [n][k]; NN: [k][n]
    constexpr int NBV  = TB ? 4 : (BN / 32);    // float4 loads per thread for B

    __shared__ uint32_t As[BM * ASTR];
    __shared__ uint32_t Bs[TB ? (BN * 36) : (32 * (BN + 4))];

    const int tid  = threadIdx.x;
    const int wid  = tid >> 5;
    const int lane = tid & 31;
    const int g    = lane >> 2;
    const int tg   = lane & 3;
    const int wm   = (wid / WGN) * WM;
    const int wn   = (wid % WGN) * WN;

    const int z = blockIdx.z;
    const long long zb = z / HH, zh = z % HH;
    const float* Ab = A + zb * sA1 + zh * sA2 + (size_t)blockIdx.y * BM * lda;
    const float* Bb = B + zb * sB1 + zh * sB2 +
                      (TB ? (size_t)blockIdx.x * BN * ldb : (size_t)blockIdx.x * BN);
    float* Cb = C + zb * sC1 + zh * sC2 +
                (size_t)blockIdx.y * BM * ldc + (size_t)blockIdx.x * BN;

    float4 fa[4], fb[NBV];

    auto loadA = [&](int k0) {
#pragma unroll
        for (int i = 0; i < 4; i++) {
            int idx = tid + i * 256;                 // 1024 float4 = 128x32
            fa[i] = *(const float4*)(Ab + (size_t)(idx >> 3) * lda + k0 + (idx & 7) * 4);
        }
    };
    auto loadB = [&](int k0) {
#pragma unroll
        for (int i = 0; i < NBV; i++) {
            int idx = tid + i * 256;
            if (TB) {   // B rows are n, cols k (128 x 32)
                fb[i] = *(const float4*)(Bb + (size_t)(idx >> 3) * ldb + k0 + (idx & 7) * 4);
            } else {    // B rows are k, cols n (32 x BN)
                int r = idx / (BN / 4), cv = idx % (BN / 4);
                fb[i] = *(const float4*)(Bb + (size_t)(k0 + r) * ldb + cv * 4);
            }
        }
    };
    auto storeA = [&]() {
#pragma unroll
        for (int i = 0; i < 4; i++) {
            int idx = tid + i * 256;
            int m = idx >> 3, cv = idx & 7;
            uint4 u = make_uint4(f2tf(fa[i].x), f2tf(fa[i].y), f2tf(fa[i].z), f2tf(fa[i].w));
            *(uint4*)&As[m * ASTR + cv * 4] = u;
        }
    };
    auto storeB = [&]() {
#pragma unroll
        for (int i = 0; i < NBV; i++) {
            int idx = tid + i * 256;
            uint4 u = make_uint4(f2tf(fb[i].x), f2tf(fb[i].y), f2tf(fb[i].z), f2tf(fb[i].w));
            if (TB) {
                int n = idx >> 3, cv = idx & 7;
                *(uint4*)&Bs[n * BSTR + cv * 4] = u;
            } else {
                int r = idx / (BN / 4), cv = idx % (BN / 4);
                *(uint4*)&Bs[r * BSTR + cv * 4] = u;
            }
        }
    };

    float c[MI][NJ][4];
#pragma unroll
    for (int mi = 0; mi < MI; mi++)
#pragma unroll
        for (int j = 0; j < NJ; j++)
#pragma unroll
            for (int r = 0; r < 4; r++) c[mi][j][r] = 0.f;

    const int nK = K / 32;
    loadA(0);
    loadB(0);

    for (int kc = 0; kc < nK; kc++) {
        storeA();
        storeB();
        __syncthreads();
        if (kc + 1 < nK) { loadA((kc + 1) * 32); loadB((kc + 1) * 32); }

#pragma unroll
        for (int kk = 0; kk < 4; kk++) {
            const int ks = kk * 8;
            uint32_t af[MI][4], bf[NJ][2];
#pragma unroll
            for (int mi = 0; mi < MI; mi++) {
                int m = wm + mi * 16 + g;
                af[mi][0] = As[m * ASTR + ks + tg];
                af[mi][1] = As[(m + 8) * ASTR + ks + tg];
                af[mi][2] = As[m * ASTR + ks + tg + 4];
                af[mi][3] = As[(m + 8) * ASTR + ks + tg + 4];
            }
#pragma unroll
            for (int j = 0; j < NJ; j++) {
                int n = wn + j * 8 + g;
                if (TB) {
                    bf[j][0] = Bs[n * BSTR + ks + tg];
                    bf[j][1] = Bs[n * BSTR + ks + tg + 4];
                } else {
                    bf[j][0] = Bs[(ks + tg) * BSTR + n];
                    bf[j][1] = Bs[(ks + tg + 4) * BSTR + n];
                }
            }
#pragma unroll
            for (int mi = 0; mi < MI; mi++)
#pragma unroll
                for (int j = 0; j < NJ; j++) mma8(c[mi][j], af[mi], bf[j]);
        }
        __syncthreads();
    }

    // epilogue
#pragma unroll
    for (int mi = 0; mi < MI; mi++) {
        int r0 = wm + mi * 16 + g;
#pragma unroll
        for (int j = 0; j < NJ; j++) {
            int col = wn + j * 8 + tg * 2;
            float2 bb = make_float2(0.f, 0.f);
            if (bias) bb = *(const float2*)(bias + (size_t)blockIdx.x * BN + col);
            float v0 = c[mi][j][0] * alpha + bb.x;
            float v1 = c[mi][j][1] * alpha + bb.y;
            float v2 = c[mi][j][2] * alpha + bb.x;
            float v3 = c[mi][j][3] * alpha + bb.y;
            if (relu) {
                v0 = fmaxf(v0, 0.f); v1 = fmaxf(v1, 0.f);
                v2 = fmaxf(v2, 0.f); v3 = fmaxf(v3, 0.f);
            }
            *(float2*)(Cb + (size_t)r0 * ldc + col)       = make_float2(v0, v1);
            *(float2*)(Cb + (size_t)(r0 + 8) * ldc + col) = make_float2(v2, v3);
        }
    }
}

// ---------------- softmax, in place, one block per row ------------------------
__global__ void softmax_kernel(float* __restrict__ attn)
{
    size_t row = blockIdx.x;
    float4* p4 = (float4*)(attn + row * SS);
    int t = threadIdx.x;            // 256 threads, 2 float4 = 8 elems each
    __shared__ float red[256];

    float4 v0 = p4[t], v1 = p4[t + 256];
    float m = fmaxf(fmaxf(fmaxf(v0.x, v0.y), fmaxf(v0.z, v0.w)),
                    fmaxf(fmaxf(v1.x, v1.y), fmaxf(v1.z, v1.w)));
    red[t] = m; __syncthreads();
    for (int s = 128; s > 0; s >>= 1) { if (t < s) red[t] = fmaxf(red[t], red[t + s]); __syncthreads(); }
    m = red[0]; __syncthreads();

    v0.x = __expf(v0.x - m); v0.y = __expf(v0.y - m); v0.z = __expf(v0.z - m); v0.w = __expf(v0.w - m);
    v1.x = __expf(v1.x - m); v1.y = __expf(v1.y - m); v1.z = __expf(v1.z - m); v1.w = __expf(v1.w - m);
    float sum = v0.x + v0.y + v0.z + v0.w + v1.x + v1.y + v1.z + v1.w;
    red[t] = sum; __syncthreads();
    for (int s = 128; s > 0; s >>= 1) { if (t < s) red[t] += red[t + s]; __syncthreads(); }
    float inv = 1.0f / red[0];

    v0.x *= inv; v0.y *= inv; v0.z *= inv; v0.w *= inv;
    v1.x *= inv; v1.y *= inv; v1.z *= inv; v1.w *= inv;
    p4[t] = v0; p4[t + 256] = v1;
}

// ---------------- residual + layernorm, one block per row ---------------------
__global__ void add_ln_kernel(const float* __restrict__ x, const float* __restrict__ y,
                              const float* __restrict__ g, const float* __restrict__ be,
                              float* __restrict__ out)
{
    size_t row = blockIdx.x;
    const float* px = x + row * DD;
    const float* py = y + row * DD;
    float* po = out + row * DD;
    int t = threadIdx.x;   // 256 threads, 3 elems each
    __shared__ float red[256];

    float a0 = px[t]       + py[t];
    float a1 = px[t + 256] + py[t + 256];
    float a2 = px[t + 512] + py[t + 512];

    red[t] = a0 + a1 + a2; __syncthreads();
    for (int s = 128; s > 0; s >>= 1) { if (t < s) red[t] += red[t + s]; __syncthreads(); }
    float mean = red[0] * (1.0f / DD); __syncthreads();

    float d0 = a0 - mean, d1 = a1 - mean, d2 = a2 - mean;
    red[t] = d0 * d0 + d1 * d1 + d2 * d2; __syncthreads();
    for (int s = 128; s > 0; s >>= 1) { if (t < s) red[t] += red[t + s]; __syncthreads(); }
    float rstd = rsqrtf(red[0] * (1.0f / DD) + 1e-5f);

    po[t]       = d0 * rstd * g[t]       + be[t];
    po[t + 256] = d1 * rstd * g[t + 256] + be[t + 256];
    po[t + 512] = d2 * rstd * g[t + 512] + be[t + 512];
}

// ---------------- launcher ----------------------------------------------------
extern "C" void kernel_launch(void* const* d_in, const int* in_sizes, int n_in,
                              void* d_out, int out_size)
{
    const float* x   = (const float*)d_in[0];
    const float* Wq  = (const float*)d_in[1];
    const float* bq  = (const float*)d_in[2];
    const float* Wk  = (const float*)d_in[3];
    const float* bk  = (const float*)d_in[4];
    const float* Wv  = (const float*)d_in[5];
    const float* bv  = (const float*)d_in[6];
    const float* Wo  = (const float*)d_in[7];
    const float* bo  = (const float*)d_in[8];
    const float* W1  = (const float*)d_in[9];
    const float* b1  = (const float*)d_in[10];
    const float* W2  = (const float*)d_in[11];
    const float* b2  = (const float*)d_in[12];
    const float* g1  = (const float*)d_in[13];
    const float* be1 = (const float*)d_in[14];
    const float* g2  = (const float*)d_in[15];
    const float* be2 = (const float*)d_in[16];

    float* out  = (float*)d_out;                 // x2: [2,2048,768]
    float* attn = out + X2_ELEMS;                // attn_weights: [2,12,2048,2048]

    float *Qp, *Kp, *Vp, *Cp, *X1p, *T2p, *FFp;
    cudaGetSymbolAddress((void**)&Qp,  g_Q);
    cudaGetSymbolAddress((void**)&Kp,  g_K);
    cudaGetSymbolAddress((void**)&Vp,  g_V);
    cudaGetSymbolAddress((void**)&Cp,  g_ctx);
    cudaGetSymbolAddress((void**)&X1p, g_x1);
    cudaGetSymbolAddress((void**)&T2p, g_t2);
    cudaGetSymbolAddress((void**)&FFp, g_ff);

    const long long Z0 = 0;

    // Q, K, V projections: [4096,768] = x @ W + b
    gemm_tf32<128,128,64,32,false><<<dim3(DD/128, MM/128, 1), 256>>>(
        x, Wq, bq, Qp, DD, DD, DD, DD, Z0,Z0,Z0,Z0,Z0,Z0, 1.f, 0);
    gemm_tf32<128,128,64,32,false><<<dim3(DD/128, MM/128, 1), 256>>>(
        x, Wk, bk, Kp, DD, DD, DD, DD, Z0,Z0,Z0,Z0,Z0,Z0, 1.f, 0);
    gemm_tf32<128,128,64,32,false><<<dim3(DD/128, MM/128, 1), 256>>>(
        x, Wv, bv, Vp, DD, DD, DD, DD, Z0,Z0,Z0,Z0,Z0,Z0, 1.f, 0);

    // scores = Q @ K^T / 8  -> directly into output attn region
    gemm_tf32<128,128,64,32,true><<<dim3(SS/128, SS/128, BB*HH), 256>>>(
        Qp, Kp, nullptr, attn, DK, DD, DD, SS,
        (long long)SS*DD, (long long)DK,
        (long long)SS*DD, (long long)DK,
        (long long)HH*SS*SS, (long long)SS*SS, 0.125f, 0);

    softmax_kernel<<<BB*HH*SS, 256>>>(attn);

    // ctx = attn @ V (per head, N=64)
    gemm_tf32<128,64,32,32,false><<<dim3(1, SS/128, BB*HH), 256>>>(
        attn, Vp, nullptr, Cp, SS, SS, DD, DD,
        (long long)HH*SS*SS, (long long)SS*SS,
        (long long)SS*DD, (long long)DK,
        (long long)SS*DD, (long long)DK, 1.f, 0);

    // attn_out = ctx @ Wo + bo
    gemm_tf32<128,128,64,32,false><<<dim3(DD/128, MM/128, 1), 256>>>(
        Cp, Wo, bo, T2p, DD, DD, DD, DD, Z0,Z0,Z0,Z0,Z0,Z0, 1.f, 0);

    // x1 = LN(x + attn_out)
    add_ln_kernel<<<MM, 256>>>(x, T2p, g1, be1, X1p);

    // ff = relu(x1 @ W1 + b1); ff2 = ff @ W2 + b2
    gemm_tf32<128,128,64,32,false><<<dim3(DFF/128, MM/128, 1), 256>>>(
        X1p, W1, b1, FFp, DD, DD, DFF, DFF, Z0,Z0,Z0,Z0,Z0,Z0, 1.f, 1);
    gemm_tf32<128,128,64,32,false><<<dim3(DD/128, MM/128, 1), 256>>>(
        FFp, W2, b2, T2p, DFF, DFF, DD, DD, Z0,Z0,Z0,Z0,Z0,Z0, 1.f, 0);

    // x2 = LN(x1 + ff2) -> output
    add_ln_kernel<<<MM, 256>>>(X1p, T2p, g2, be2, out);
}

// round 3
// speedup vs baseline: 2.9421x; 1.1882x over previous
#include <cuda_runtime.h>
#include <cstdint>
#include <cstddef>

#define BB 2
#define SS 2048
#define DD 768
#define HH 12
#define DK 64
#define DFF 3072
#define MM (BB*SS)                 // 4096
#define X2_ELEMS ((size_t)MM*DD)   // 3145728

// ---------------- scratch (static device globals; no allocation) -------------
__device__ float g_Q[(size_t)MM*DD];
__device__ float g_K[(size_t)MM*DD];
__device__ float g_V[(size_t)MM*DD];
__device__ float g_ctx[(size_t)MM*DD];
__device__ float g_x1[(size_t)MM*DD];
__device__ float g_t2[(size_t)MM*DD];
__device__ float g_ff[(size_t)MM*DFF];

// ---------------- helpers ----------------------------------------------------
__device__ __forceinline__ uint32_t f2tf(float f) {
    uint32_t u;
    asm("cvt.rna.tf32.f32 %0, %1;" : "=r"(u) : "f"(f));
    return u;
}

__device__ __forceinline__ void mma8(float* c, const uint32_t* a, const uint32_t* b) {
    asm volatile(
        "mma.sync.aligned.m16n8k8.row.col.f32.tf32.tf32.f32 "
        "{%0,%1,%2,%3},{%4,%5,%6,%7},{%8,%9},{%0,%1,%2,%3};\n"
        : "+f"(c[0]), "+f"(c[1]), "+f"(c[2]), "+f"(c[3])
        : "r"(a[0]), "r"(a[1]), "r"(a[2]), "r"(a[3]), "r"(b[0]), "r"(b[1]));
}

__device__ __forceinline__ void cp16(uint32_t smem_addr, const void* gptr) {
    asm volatile("cp.async.cg.shared.global [%0], [%1], 16;\n"
                 :: "r"(smem_addr), "l"(gptr));
}
__device__ __forceinline__ void cp_commit() {
    asm volatile("cp.async.commit_group;\n" ::: "memory");
}
template<int N>
__device__ __forceinline__ void cp_wait() {
    asm volatile("cp.async.wait_group %0;\n" :: "n"(N) : "memory");
}

// ---------------- generic TF32 tensor-core GEMM (cp.async double buffer) -----
// C[M,N] = alpha * A @ op(B) + bias, optional relu.
// A: row-major m×k (lda). TB=false: B row-major k×n (ldb). TB=true: B row-major n×k.
// Per-z offsets: off = (z/HH)*s1 + (z%HH)*s2 for each of A, B, C.
// Block tile BM×BN, BK=32, 256 threads (8 warps), warp tile WM×WN, mma m16n8k8.
template<int BM, int BN, int WM, int WN, bool TB>
__global__ void __launch_bounds__(256, 2) gemm_tf32(
    const float* __restrict__ A, const float* __restrict__ B,
    const float* __restrict__ bias, float* __restrict__ C,
    int K, int lda, int ldb, int ldc,
    long long sA1, long long sA2, long long sB1, long long sB2,
    long long sC1, long long sC2, float alpha, int relu)
{
    constexpr int MI  = WM / 16;
    constexpr int NJ  = WN / 8;
    constexpr int WGN = BN / WN;
    constexpr int ASTR = 36;                    // [m][k] stride -> bank = (4m+k)%32
    constexpr int BSTR = TB ? 36 : (BN + 4);    // TB: [n][k]; NN: [k][n]
    constexpr int ASZ  = BM * ASTR;
    constexpr int BSZ  = TB ? (BN * 36) : (32 * (BN + 4));
    constexpr int NAV  = BM * 8 / 256;          // 16B chunks per thread for A
    constexpr int NBV  = TB ? (BN * 8 / 256) : (8 * BN / 256);

    __shared__ float As[2 * ASZ];
    __shared__ float Bs[2 * BSZ];

    const int tid  = threadIdx.x;
    const int wid  = tid >> 5;
    const int lane = tid & 31;
    const int g    = lane >> 2;
    const int tg   = lane & 3;
    const int wm   = (wid / WGN) * WM;
    const int wn   = (wid % WGN) * WN;

    const int z = blockIdx.z;
    const long long zb = z / HH, zh = z % HH;
    const float* Ab = A + zb * sA1 + zh * sA2 + (size_t)blockIdx.y * BM * lda;
    const float* Bb = B + zb * sB1 + zh * sB2 +
                      (TB ? (size_t)blockIdx.x * BN * ldb : (size_t)blockIdx.x * BN);
    float* Cb = C + zb * sC1 + zh * sC2 +
                (size_t)blockIdx.y * BM * ldc + (size_t)blockIdx.x * BN;

    const uint32_t sA_base = (uint32_t)__cvta_generic_to_shared(As);
    const uint32_t sB_base = (uint32_t)__cvta_generic_to_shared(Bs);

    auto issue = [&](int k0, int st) {
        uint32_t abuf = sA_base + st * ASZ * 4;
#pragma unroll
        for (int i = 0; i < NAV; i++) {
            int idx = tid + i * 256;
            int m = idx >> 3, cv = idx & 7;
            cp16(abuf + (m * ASTR + cv * 4) * 4,
                 Ab + (size_t)m * lda + k0 + cv * 4);
        }
        uint32_t bbuf = sB_base + st * BSZ * 4;
#pragma unroll
        for (int i = 0; i < NBV; i++) {
            int idx = tid + i * 256;
            if (TB) {
                int n = idx >> 3, cv = idx & 7;
                cp16(bbuf + (n * BSTR + cv * 4) * 4,
                     Bb + (size_t)n * ldb + k0 + cv * 4);
            } else {
                int r = idx / (BN / 4), cv = idx % (BN / 4);
                cp16(bbuf + (r * BSTR + cv * 4) * 4,
                     Bb + (size_t)(k0 + r) * ldb + cv * 4);
            }
        }
        cp_commit();
    };

    float c[MI][NJ][4];
#pragma unroll
    for (int mi = 0; mi < MI; mi++)
#pragma unroll
        for (int j = 0; j < NJ; j++)
#pragma unroll
            for (int r = 0; r < 4; r++) c[mi][j][r] = 0.f;

    const int nK = K / 32;
    issue(0, 0);

    for (int kc = 0; kc < nK; kc++) {
        const int st = kc & 1;
        if (kc + 1 < nK) {
            issue((kc + 1) * 32, st ^ 1);
            cp_wait<1>();
        } else {
            cp_wait<0>();
        }
        __syncthreads();

        const float* Ac = As + st * ASZ;
        const float* Bc = Bs + st * BSZ;
#pragma unroll
        for (int kk = 0; kk < 4; kk++) {
            const int ks = kk * 8;
            uint32_t af[MI][4], bf[NJ][2];
#pragma unroll
            for (int mi = 0; mi < MI; mi++) {
                int m = wm + mi * 16 + g;
                af[mi][0] = f2tf(Ac[m * ASTR + ks + tg]);
                af[mi][1] = f2tf(Ac[(m + 8) * ASTR + ks + tg]);
                af[mi][2] = f2tf(Ac[m * ASTR + ks + tg + 4]);
                af[mi][3] = f2tf(Ac[(m + 8) * ASTR + ks + tg + 4]);
            }
#pragma unroll
            for (int j = 0; j < NJ; j++) {
                int n = wn + j * 8 + g;
                if (TB) {
                    bf[j][0] = f2tf(Bc[n * BSTR + ks + tg]);
                    bf[j][1] = f2tf(Bc[n * BSTR + ks + tg + 4]);
                } else {
                    bf[j][0] = f2tf(Bc[(ks + tg) * BSTR + n]);
                    bf[j][1] = f2tf(Bc[(ks + tg + 4) * BSTR + n]);
                }
            }
#pragma unroll
            for (int mi = 0; mi < MI; mi++)
#pragma unroll
                for (int j = 0; j < NJ; j++) mma8(c[mi][j], af[mi], bf[j]);
        }
        __syncthreads();
    }

    // epilogue
#pragma unroll
    for (int mi = 0; mi < MI; mi++) {
        int r0 = wm + mi * 16 + g;
#pragma unroll
        for (int j = 0; j < NJ; j++) {
            int col = wn + j * 8 + tg * 2;
            float2 bb = make_float2(0.f, 0.f);
            if (bias) bb = *(const float2*)(bias + (size_t)blockIdx.x * BN + col);
            float v0 = c[mi][j][0] * alpha + bb.x;
            float v1 = c[mi][j][1] * alpha + bb.y;
            float v2 = c[mi][j][2] * alpha + bb.x;
            float v3 = c[mi][j][3] * alpha + bb.y;
            if (relu) {
                v0 = fmaxf(v0, 0.f); v1 = fmaxf(v1, 0.f);
                v2 = fmaxf(v2, 0.f); v3 = fmaxf(v3, 0.f);
            }
            *(float2*)(Cb + (size_t)r0 * ldc + col)       = make_float2(v0, v1);
            *(float2*)(Cb + (size_t)(r0 + 8) * ldc + col) = make_float2(v2, v3);
        }
    }
}

// ---------------- softmax, in place, one block per row ------------------------
__global__ void softmax_kernel(float* __restrict__ attn)
{
    size_t row = blockIdx.x;
    float4* p4 = (float4*)(attn + row * SS);
    int t = threadIdx.x;            // 256 threads, 2 float4 = 8 elems each
    __shared__ float red[256];

    float4 v0 = p4[t], v1 = p4[t + 256];
    float m = fmaxf(fmaxf(fmaxf(v0.x, v0.y), fmaxf(v0.z, v0.w)),
                    fmaxf(fmaxf(v1.x, v1.y), fmaxf(v1.z, v1.w)));
    red[t] = m; __syncthreads();
    for (int s = 128; s > 0; s >>= 1) { if (t < s) red[t] = fmaxf(red[t], red[t + s]); __syncthreads(); }
    m = red[0]; __syncthreads();

    v0.x = __expf(v0.x - m); v0.y = __expf(v0.y - m); v0.z = __expf(v0.z - m); v0.w = __expf(v0.w - m);
    v1.x = __expf(v1.x - m); v1.y = __expf(v1.y - m); v1.z = __expf(v1.z - m); v1.w = __expf(v1.w - m);
    float sum = v0.x + v0.y + v0.z + v0.w + v1.x + v1.y + v1.z + v1.w;
    red[t] = sum; __syncthreads();
    for (int s = 128; s > 0; s >>= 1) { if (t < s) red[t] += red[t + s]; __syncthreads(); }
    float inv = 1.0f / red[0];

    v0.x *= inv; v0.y *= inv; v0.z *= inv; v0.w *= inv;
    v1.x *= inv; v1.y *= inv; v1.z *= inv; v1.w *= inv;
    p4[t] = v0; p4[t + 256] = v1;
}

// ---------------- residual + layernorm, one block per row ---------------------
__global__ void add_ln_kernel(const float* __restrict__ x, const float* __restrict__ y,
                              const float* __restrict__ g, const float* __restrict__ be,
                              float* __restrict__ out)
{
    size_t row = blockIdx.x;
    const float* px = x + row * DD;
    const float* py = y + row * DD;
    float* po = out + row * DD;
    int t = threadIdx.x;   // 256 threads, 3 elems each
    __shared__ float red[256];

    float a0 = px[t]       + py[t];
    float a1 = px[t + 256] + py[t + 256];
    float a2 = px[t + 512] + py[t + 512];

    red[t] = a0 + a1 + a2; __syncthreads();
    for (int s = 128; s > 0; s >>= 1) { if (t < s) red[t] += red[t + s]; __syncthreads(); }
    float mean = red[0] * (1.0f / DD); __syncthreads();

    float d0 = a0 - mean, d1 = a1 - mean, d2 = a2 - mean;
    red[t] = d0 * d0 + d1 * d1 + d2 * d2; __syncthreads();
    for (int s = 128; s > 0; s >>= 1) { if (t < s) red[t] += red[t + s]; __syncthreads(); }
    float rstd = rsqrtf(red[0] * (1.0f / DD) + 1e-5f);

    po[t]       = d0 * rstd * g[t]       + be[t];
    po[t + 256] = d1 * rstd * g[t + 256] + be[t + 256];
    po[t + 512] = d2 * rstd * g[t + 512] + be[t + 512];
}

// ---------------- launcher ----------------------------------------------------
extern "C" void kernel_launch(void* const* d_in, const int* in_sizes, int n_in,
                              void* d_out, int out_size)
{
    const float* x   = (const float*)d_in[0];
    const float* Wq  = (const float*)d_in[1];
    const float* bq  = (const float*)d_in[2];
    const float* Wk  = (const float*)d_in[3];
    const float* bk  = (const float*)d_in[4];
    const float* Wv  = (const float*)d_in[5];
    const float* bv  = (const float*)d_in[6];
    const float* Wo  = (const float*)d_in[7];
    const float* bo  = (const float*)d_in[8];
    const float* W1  = (const float*)d_in[9];
    const float* b1  = (const float*)d_in[10];
    const float* W2  = (const float*)d_in[11];
    const float* b2  = (const float*)d_in[12];
    const float* g1  = (const float*)d_in[13];
    const float* be1 = (const float*)d_in[14];
    const float* g2  = (const float*)d_in[15];
    const float* be2 = (const float*)d_in[16];

    float* out  = (float*)d_out;                 // x2: [2,2048,768]
    float* attn = out + X2_ELEMS;                // attn_weights: [2,12,2048,2048]

    float *Qp, *Kp, *Vp, *Cp, *X1p, *T2p, *FFp;
    cudaGetSymbolAddress((void**)&Qp,  g_Q);
    cudaGetSymbolAddress((void**)&Kp,  g_K);
    cudaGetSymbolAddress((void**)&Vp,  g_V);
    cudaGetSymbolAddress((void**)&Cp,  g_ctx);
    cudaGetSymbolAddress((void**)&X1p, g_x1);
    cudaGetSymbolAddress((void**)&T2p, g_t2);
    cudaGetSymbolAddress((void**)&FFp, g_ff);

    const long long Z0 = 0;

    // Q, K, V projections: [4096,768] = x @ W + b
    gemm_tf32<128,128,64,32,false><<<dim3(DD/128, MM/128, 1), 256>>>(
        x, Wq, bq, Qp, DD, DD, DD, DD, Z0,Z0,Z0,Z0,Z0,Z0, 1.f, 0);
    gemm_tf32<128,128,64,32,false><<<dim3(DD/128, MM/128, 1), 256>>>(
        x, Wk, bk, Kp, DD, DD, DD, DD, Z0,Z0,Z0,Z0,Z0,Z0, 1.f, 0);
    gemm_tf32<128,128,64,32,false><<<dim3(DD/128, MM/128, 1), 256>>>(
        x, Wv, bv, Vp, DD, DD, DD, DD, Z0,Z0,Z0,Z0,Z0,Z0, 1.f, 0);

    // scores = Q @ K^T / 8  -> directly into output attn region
    gemm_tf32<128,128,64,32,true><<<dim3(SS/128, SS/128, BB*HH), 256>>>(
        Qp, Kp, nullptr, attn, DK, DD, DD, SS,
        (long long)SS*DD, (long long)DK,
        (long long)SS*DD, (long long)DK,
        (long long)HH*SS*SS, (long long)SS*SS, 0.125f, 0);

    softmax_kernel<<<BB*HH*SS, 256>>>(attn);

    // ctx = attn @ V (per head, N=64)
    gemm_tf32<128,64,32,32,false><<<dim3(1, SS/128, BB*HH), 256>>>(
        attn, Vp, nullptr, Cp, SS, SS, DD, DD,
        (long long)HH*SS*SS, (long long)SS*SS,
        (long long)SS*DD, (long long)DK,
        (long long)SS*DD, (long long)DK, 1.f, 0);

    // attn_out = ctx @ Wo + bo
    gemm_tf32<128,128,64,32,false><<<dim3(DD/128, MM/128, 1), 256>>>(
        Cp, Wo, bo, T2p, DD, DD, DD, DD, Z0,Z0,Z0,Z0,Z0,Z0, 1.f, 0);

    // x1 = LN(x + attn_out)
    add_ln_kernel<<<MM, 256>>>(x, T2p, g1, be1, X1p);

    // ff = relu(x1 @ W1 + b1); ff2 = ff @ W2 + b2
    gemm_tf32<128,128,64,32,false><<<dim3(DFF/128, MM/128, 1), 256>>>(
        X1p, W1, b1, FFp, DD, DD, DFF, DFF, Z0,Z0,Z0,Z0,Z0,Z0, 1.f, 1);
    gemm_tf32<128,128,64,32,false><<<dim3(DD/128, MM/128, 1), 256>>>(
        FFp, W2, b2, T2p, DFF, DFF, DD, DD, Z0,Z0,Z0,Z0,Z0,Z0, 1.f, 0);

    // x2 = LN(x1 + ff2) -> output
    add_ln_kernel<<<MM, 256>>>(X1p, T2p, g2, be2, out);
}

// round 4
// speedup vs baseline: 3.2238x; 1.0957x over previous
#include <cuda_runtime.h>
#include <cstdint>
#include <cstddef>

#define BB 2
#define SS 2048
#define DD 768
#define HH 12
#define DK 64
#define DFF 3072
#define MM (BB*SS)                 // 4096
#define X2_ELEMS ((size_t)MM*DD)   // 3145728

// ---------------- scratch (static device globals; no allocation) -------------
__device__ float g_Q[(size_t)MM*DD];
__device__ float g_K[(size_t)MM*DD];
__device__ float g_V[(size_t)MM*DD];
__device__ float g_ctx[(size_t)MM*DD];
__device__ float g_x1[(size_t)MM*DD];
__device__ float g_t2[(size_t)MM*DD];
__device__ float g_ff[(size_t)MM*DFF];

// ---------------- helpers ----------------------------------------------------
// NOTE: we feed raw fp32 bits to the tf32 MMA (hardware reads the top 19 bits;
// this is truncation instead of round-to-nearest -> rel_err ~2x, still << 1e-3).
__device__ __forceinline__ void mma8(float* c, const uint32_t* a, const uint32_t* b) {
    asm volatile(
        "mma.sync.aligned.m16n8k8.row.col.f32.tf32.tf32.f32 "
        "{%0,%1,%2,%3},{%4,%5,%6,%7},{%8,%9},{%0,%1,%2,%3};\n"
        : "+f"(c[0]), "+f"(c[1]), "+f"(c[2]), "+f"(c[3])
        : "r"(a[0]), "r"(a[1]), "r"(a[2]), "r"(a[3]), "r"(b[0]), "r"(b[1]));
}

__device__ __forceinline__ void cp16(uint32_t smem_addr, const void* gptr) {
    asm volatile("cp.async.cg.shared.global [%0], [%1], 16;\n"
                 :: "r"(smem_addr), "l"(gptr));
}
__device__ __forceinline__ void cp_commit() {
    asm volatile("cp.async.commit_group;\n" ::: "memory");
}
template<int N>
__device__ __forceinline__ void cp_wait() {
    asm volatile("cp.async.wait_group %0;\n" :: "n"(N) : "memory");
}

// ---------------- generic TF32 tensor-core GEMM (cp.async double buffer) -----
// C[M,N] = alpha * A @ op(B) + bias, optional relu.
// k-permutation trick: mma k-slice local cols (tg, tg+4) are mapped to physical
// cols (2tg, 2tg+1) consistently for A and B, enabling LDS.64 fragment loads.
// Stride 40 makes both the LDS.64 reads and the cp.async stores conflict-free.
template<int BM, int BN, int WM, int WN, bool TB>
__global__ void __launch_bounds__(256, 2) gemm_tf32(
    const float* __restrict__ A, const float* __restrict__ B,
    const float* __restrict__ bias, float* __restrict__ C,
    int K, int lda, int ldb, int ldc,
    long long sA1, long long sA2, long long sB1, long long sB2,
    long long sC1, long long sC2, float alpha, int relu)
{
    constexpr int MI  = WM / 16;
    constexpr int NJ  = WN / 8;
    constexpr int WGN = BN / WN;
    constexpr int ASTR = 40;                    // [m][k] -> LDS.64 banks 8g+2tg
    constexpr int BSTR = TB ? 40 : (BN + 4);    // TB: [n][k]; NN: [k][n]
    constexpr int ASZ  = BM * ASTR;
    constexpr int BSZ  = TB ? (BN * 40) : (32 * (BN + 4));
    constexpr int NAV  = BM * 8 / 256;          // 16B chunks per thread for A
    constexpr int NBV  = TB ? (BN * 8 / 256) : (8 * BN / 256);

    __shared__ float As[2 * ASZ];
    __shared__ float Bs[2 * BSZ];

    const int tid  = threadIdx.x;
    const int wid  = tid >> 5;
    const int lane = tid & 31;
    const int g    = lane >> 2;
    const int tg   = lane & 3;
    const int wm   = (wid / WGN) * WM;
    const int wn   = (wid % WGN) * WN;

    const int z = blockIdx.z;
    const long long zb = z / HH, zh = z % HH;
    const float* Ab = A + zb * sA1 + zh * sA2 + (size_t)blockIdx.y * BM * lda;
    const float* Bb = B + zb * sB1 + zh * sB2 +
                      (TB ? (size_t)blockIdx.x * BN * ldb : (size_t)blockIdx.x * BN);
    float* Cb = C + zb * sC1 + zh * sC2 +
                (size_t)blockIdx.y * BM * ldc + (size_t)blockIdx.x * BN;

    const uint32_t sA_base = (uint32_t)__cvta_generic_to_shared(As);
    const uint32_t sB_base = (uint32_t)__cvta_generic_to_shared(Bs);

    auto issue = [&](int k0, int st) {
        uint32_t abuf = sA_base + st * ASZ * 4;
#pragma unroll
        for (int i = 0; i < NAV; i++) {
            int idx = tid + i * 256;
            int m = idx >> 3, cv = idx & 7;
            cp16(abuf + (m * ASTR + cv * 4) * 4,
                 Ab + (size_t)m * lda + k0 + cv * 4);
        }
        uint32_t bbuf = sB_base + st * BSZ * 4;
#pragma unroll
        for (int i = 0; i < NBV; i++) {
            int idx = tid + i * 256;
            if (TB) {
                int n = idx >> 3, cv = idx & 7;
                cp16(bbuf + (n * BSTR + cv * 4) * 4,
                     Bb + (size_t)n * ldb + k0 + cv * 4);
            } else {
                int r = idx / (BN / 4), cv = idx % (BN / 4);
                cp16(bbuf + (r * BSTR + cv * 4) * 4,
                     Bb + (size_t)(k0 + r) * ldb + cv * 4);
            }
        }
        cp_commit();
    };

    float c[MI][NJ][4];
#pragma unroll
    for (int mi = 0; mi < MI; mi++)
#pragma unroll
        for (int j = 0; j < NJ; j++)
#pragma unroll
            for (int r = 0; r < 4; r++) c[mi][j][r] = 0.f;

    const int nK = K / 32;
    issue(0, 0);

    for (int kc = 0; kc < nK; kc++) {
        const int st = kc & 1;
        if (kc + 1 < nK) {
            issue((kc + 1) * 32, st ^ 1);
            cp_wait<1>();
        } else {
            cp_wait<0>();
        }
        __syncthreads();

        const float* Ac = As + st * ASZ;
        const float* Bc = Bs + st * BSZ;
#pragma unroll
        for (int kk = 0; kk < 4; kk++) {
            const int ks = kk * 8;
            uint32_t af[MI][4], bf[NJ][2];
#pragma unroll
            for (int mi = 0; mi < MI; mi++) {
                int m = wm + mi * 16 + g;
                // physical cols 2tg, 2tg+1 <-> mma local cols tg, tg+4
                float2 p0 = *(const float2*)&Ac[m * ASTR + ks + 2 * tg];
                float2 p1 = *(const float2*)&Ac[(m + 8) * ASTR + ks + 2 * tg];
                af[mi][0] = __float_as_uint(p0.x);
                af[mi][1] = __float_as_uint(p1.x);
                af[mi][2] = __float_as_uint(p0.y);
                af[mi][3] = __float_as_uint(p1.y);
            }
#pragma unroll
            for (int j = 0; j < NJ; j++) {
                int n = wn + j * 8 + g;
                if (TB) {
                    float2 q = *(const float2*)&Bc[n * BSTR + ks + 2 * tg];
                    bf[j][0] = __float_as_uint(q.x);
                    bf[j][1] = __float_as_uint(q.y);
                } else {
                    bf[j][0] = __float_as_uint(Bc[(ks + 2 * tg)     * BSTR + n]);
                    bf[j][1] = __float_as_uint(Bc[(ks + 2 * tg + 1) * BSTR + n]);
                }
            }
#pragma unroll
            for (int mi = 0; mi < MI; mi++)
#pragma unroll
                for (int j = 0; j < NJ; j++) mma8(c[mi][j], af[mi], bf[j]);
        }
        __syncthreads();
    }

    // epilogue
#pragma unroll
    for (int mi = 0; mi < MI; mi++) {
        int r0 = wm + mi * 16 + g;
#pragma unroll
        for (int j = 0; j < NJ; j++) {
            int col = wn + j * 8 + tg * 2;
            float2 bb = make_float2(0.f, 0.f);
            if (bias) bb = *(const float2*)(bias + (size_t)blockIdx.x * BN + col);
            float v0 = c[mi][j][0] * alpha + bb.x;
            float v1 = c[mi][j][1] * alpha + bb.y;
            float v2 = c[mi][j][2] * alpha + bb.x;
            float v3 = c[mi][j][3] * alpha + bb.y;
            if (relu) {
                v0 = fmaxf(v0, 0.f); v1 = fmaxf(v1, 0.f);
                v2 = fmaxf(v2, 0.f); v3 = fmaxf(v3, 0.f);
            }
            *(float2*)(Cb + (size_t)r0 * ldc + col)       = make_float2(v0, v1);
            *(float2*)(Cb + (size_t)(r0 + 8) * ldc + col) = make_float2(v2, v3);
        }
    }
}

// ---------------- softmax, in place, one block per row ------------------------
__global__ void softmax_kernel(float* __restrict__ attn)
{
    size_t row = blockIdx.x;
    float4* p4 = (float4*)(attn + row * SS);
    int t = threadIdx.x;            // 256 threads, 2 float4 = 8 elems each
    __shared__ float red[256];

    float4 v0 = p4[t], v1 = p4[t + 256];
    float m = fmaxf(fmaxf(fmaxf(v0.x, v0.y), fmaxf(v0.z, v0.w)),
                    fmaxf(fmaxf(v1.x, v1.y), fmaxf(v1.z, v1.w)));
    red[t] = m; __syncthreads();
    for (int s = 128; s > 0; s >>= 1) { if (t < s) red[t] = fmaxf(red[t], red[t + s]); __syncthreads(); }
    m = red[0]; __syncthreads();

    v0.x = __expf(v0.x - m); v0.y = __expf(v0.y - m); v0.z = __expf(v0.z - m); v0.w = __expf(v0.w - m);
    v1.x = __expf(v1.x - m); v1.y = __expf(v1.y - m); v1.z = __expf(v1.z - m); v1.w = __expf(v1.w - m);
    float sum = v0.x + v0.y + v0.z + v0.w + v1.x + v1.y + v1.z + v1.w;
    red[t] = sum; __syncthreads();
    for (int s = 128; s > 0; s >>= 1) { if (t < s) red[t] += red[t + s]; __syncthreads(); }
    float inv = 1.0f / red[0];

    v0.x *= inv; v0.y *= inv; v0.z *= inv; v0.w *= inv;
    v1.x *= inv; v1.y *= inv; v1.z *= inv; v1.w *= inv;
    p4[t] = v0; p4[t + 256] = v1;
}

// ---------------- residual + layernorm, one block per row ---------------------
__global__ void add_ln_kernel(const float* __restrict__ x, const float* __restrict__ y,
                              const float* __restrict__ g, const float* __restrict__ be,
                              float* __restrict__ out)
{
    size_t row = blockIdx.x;
    const float* px = x + row * DD;
    const float* py = y + row * DD;
    float* po = out + row * DD;
    int t = threadIdx.x;   // 256 threads, 3 elems each
    __shared__ float red[256];

    float a0 = px[t]       + py[t];
    float a1 = px[t + 256] + py[t + 256];
    float a2 = px[t + 512] + py[t + 512];

    red[t] = a0 + a1 + a2; __syncthreads();
    for (int s = 128; s > 0; s >>= 1) { if (t < s) red[t] += red[t + s]; __syncthreads(); }
    float mean = red[0] * (1.0f / DD); __syncthreads();

    float d0 = a0 - mean, d1 = a1 - mean, d2 = a2 - mean;
    red[t] = d0 * d0 + d1 * d1 + d2 * d2; __syncthreads();
    for (int s = 128; s > 0; s >>= 1) { if (t < s) red[t] += red[t + s]; __syncthreads(); }
    float rstd = rsqrtf(red[0] * (1.0f / DD) + 1e-5f);

    po[t]       = d0 * rstd * g[t]       + be[t];
    po[t + 256] = d1 * rstd * g[t + 256] + be[t + 256];
    po[t + 512] = d2 * rstd * g[t + 512] + be[t + 512];
}

// ---------------- launcher ----------------------------------------------------
extern "C" void kernel_launch(void* const* d_in, const int* in_sizes, int n_in,
                              void* d_out, int out_size)
{
    const float* x   = (const float*)d_in[0];
    const float* Wq  = (const float*)d_in[1];
    const float* bq  = (const float*)d_in[2];
    const float* Wk  = (const float*)d_in[3];
    const float* bk  = (const float*)d_in[4];
    const float* Wv  = (const float*)d_in[5];
    const float* bv  = (const float*)d_in[6];
    const float* Wo  = (const float*)d_in[7];
    const float* bo  = (const float*)d_in[8];
    const float* W1  = (const float*)d_in[9];
    const float* b1  = (const float*)d_in[10];
    const float* W2  = (const float*)d_in[11];
    const float* b2  = (const float*)d_in[12];
    const float* g1  = (const float*)d_in[13];
    const float* be1 = (const float*)d_in[14];
    const float* g2  = (const float*)d_in[15];
    const float* be2 = (const float*)d_in[16];

    float* out  = (float*)d_out;                 // x2: [2,2048,768]
    float* attn = out + X2_ELEMS;                // attn_weights: [2,12,2048,2048]

    float *Qp, *Kp, *Vp, *Cp, *X1p, *T2p, *FFp;
    cudaGetSymbolAddress((void**)&Qp,  g_Q);
    cudaGetSymbolAddress((void**)&Kp,  g_K);
    cudaGetSymbolAddress((void**)&Vp,  g_V);
    cudaGetSymbolAddress((void**)&Cp,  g_ctx);
    cudaGetSymbolAddress((void**)&X1p, g_x1);
    cudaGetSymbolAddress((void**)&T2p, g_t2);
    cudaGetSymbolAddress((void**)&FFp, g_ff);

    const long long Z0 = 0;

    // Q, K, V projections: [4096,768] = x @ W + b
    gemm_tf32<128,128,64,32,false><<<dim3(DD/128, MM/128, 1), 256>>>(
        x, Wq, bq, Qp, DD, DD, DD, DD, Z0,Z0,Z0,Z0,Z0,Z0, 1.f, 0);
    gemm_tf32<128,128,64,32,false><<<dim3(DD/128, MM/128, 1), 256>>>(
        x, Wk, bk, Kp, DD, DD, DD, DD, Z0,Z0,Z0,Z0,Z0,Z0, 1.f, 0);
    gemm_tf32<128,128,64,32,false><<<dim3(DD/128, MM/128, 1), 256>>>(
        x, Wv, bv, Vp, DD, DD, DD, DD, Z0,Z0,Z0,Z0,Z0,Z0, 1.f, 0);

    // scores = Q @ K^T / 8  -> directly into output attn region
    gemm_tf32<128,128,64,32,true><<<dim3(SS/128, SS/128, BB*HH), 256>>>(
        Qp, Kp, nullptr, attn, DK, DD, DD, SS,
        (long long)SS*DD, (long long)DK,
        (long long)SS*DD, (long long)DK,
        (long long)HH*SS*SS, (long long)SS*SS, 0.125f, 0);

    softmax_kernel<<<BB*HH*SS, 256>>>(attn);

    // ctx = attn @ V (per head, N=64)
    gemm_tf32<128,64,32,32,false><<<dim3(1, SS/128, BB*HH), 256>>>(
        attn, Vp, nullptr, Cp, SS, SS, DD, DD,
        (long long)HH*SS*SS, (long long)SS*SS,
        (long long)SS*DD, (long long)DK,
        (long long)SS*DD, (long long)DK, 1.f, 0);

    // attn_out = ctx @ Wo + bo
    gemm_tf32<128,128,64,32,false><<<dim3(DD/128, MM/128, 1), 256>>>(
        Cp, Wo, bo, T2p, DD, DD, DD, DD, Z0,Z0,Z0,Z0,Z0,Z0, 1.f, 0);

    // x1 = LN(x + attn_out)
    add_ln_kernel<<<MM, 256>>>(x, T2p, g1, be1, X1p);

    // ff = relu(x1 @ W1 + b1); ff2 = ff @ W2 + b2
    gemm_tf32<128,128,64,32,false><<<dim3(DFF/128, MM/128, 1), 256>>>(
        X1p, W1, b1, FFp, DD, DD, DFF, DFF, Z0,Z0,Z0,Z0,Z0,Z0, 1.f, 1);
    gemm_tf32<128,128,64,32,false><<<dim3(DD/128, MM/128, 1), 256>>>(
        FFp, W2, b2, T2p, DFF, DFF, DD, DD, Z0,Z0,Z0,Z0,Z0,Z0, 1.f, 0);

    // x2 = LN(x1 + ff2) -> output
    add_ln_kernel<<<MM, 256>>>(X1p, T2p, g2, be2, out);
}

// round 5
// speedup vs baseline: 3.3686x; 1.0449x over previous
#include <cuda_runtime.h>
#include <cstdint>
#include <cstddef>

#define BB 2
#define SS 2048
#define DD 768
#define HH 12
#define DK 64
#define DFF 3072
#define MM (BB*SS)                 // 4096
#define X2_ELEMS ((size_t)MM*DD)   // 3145728

// ---------------- scratch (static device globals; no allocation) -------------
__device__ float g_Q[(size_t)MM*DD];
__device__ float g_K[(size_t)MM*DD];
__device__ float g_V[(size_t)MM*DD];
__device__ float g_ctx[(size_t)MM*DD];
__device__ float g_x1[(size_t)MM*DD];
__device__ float g_t2[(size_t)MM*DD];
__device__ float g_ff[(size_t)MM*DFF];
// rounded copies of GEMM inputs
__device__ float g_xr[(size_t)MM*DD];
__device__ float g_Wqr[(size_t)DD*DD];
__device__ float g_Wkr[(size_t)DD*DD];
__device__ float g_Wvr[(size_t)DD*DD];
__device__ float g_Wor[(size_t)DD*DD];
__device__ float g_W1r[(size_t)DD*DFF];
__device__ float g_W2r[(size_t)DFF*DD];

// ---------------- helpers ----------------------------------------------------
__device__ __forceinline__ float rtf(float v) {       // round-to-nearest tf32
    uint32_t r;
    asm("cvt.rna.tf32.f32 %0, %1;" : "=r"(r) : "f"(v));
    return __uint_as_float(r);
}

__device__ __forceinline__ void mma8(float* c, const uint32_t* a, const uint32_t* b) {
    asm volatile(
        "mma.sync.aligned.m16n8k8.row.col.f32.tf32.tf32.f32 "
        "{%0,%1,%2,%3},{%4,%5,%6,%7},{%8,%9},{%0,%1,%2,%3};\n"
        : "+f"(c[0]), "+f"(c[1]), "+f"(c[2]), "+f"(c[3])
        : "r"(a[0]), "r"(a[1]), "r"(a[2]), "r"(a[3]), "r"(b[0]), "r"(b[1]));
}

__device__ __forceinline__ void cp16(uint32_t smem_addr, const void* gptr) {
    asm volatile("cp.async.cg.shared.global [%0], [%1], 16;\n"
                 :: "r"(smem_addr), "l"(gptr));
}
__device__ __forceinline__ void cp_commit() {
    asm volatile("cp.async.commit_group;\n" ::: "memory");
}
template<int N>
__device__ __forceinline__ void cp_wait() {
    asm volatile("cp.async.wait_group %0;\n" :: "n"(N) : "memory");
}

// ---------------- elementwise tf32 pre-round ---------------------------------
__global__ void round_kernel(const float4* __restrict__ in, float4* __restrict__ out, int n4)
{
    int i = blockIdx.x * blockDim.x + threadIdx.x;
    if (i < n4) {
        float4 v = in[i];
        v.x = rtf(v.x); v.y = rtf(v.y); v.z = rtf(v.z); v.w = rtf(v.w);
        out[i] = v;
    }
}

// ---------------- generic TF32 tensor-core GEMM (cp.async double buffer) -----
// All operands are pre-rounded tf32 values -> raw-bit feed is exact RNA.
// QKV=true: blockIdx.z in {0,1,2} selects (B,bias,C) triple; else z -> (zb,zh) strides.
template<int BM, int BN, int WM, int WN, bool TB, bool QKV>
__global__ void __launch_bounds__(256, 2) gemm_tf32(
    const float* __restrict__ A,
    const float* __restrict__ B0, const float* __restrict__ bias0, float* __restrict__ C0,
    const float* __restrict__ B1p, const float* __restrict__ bias1p, float* __restrict__ C1p,
    const float* __restrict__ B2p, const float* __restrict__ bias2p, float* __restrict__ C2p,
    int K, int lda, int ldb, int ldc,
    long long sA1, long long sA2, long long sB1, long long sB2,
    long long sC1, long long sC2, float alpha, int relu, int rnd)
{
    constexpr int MI  = WM / 16;
    constexpr int NJ  = WN / 8;
    constexpr int WGN = BN / WN;
    constexpr int ASTR = 40;                    // [m][k] -> LDS.64 banks 8g+2tg
    constexpr int BSTR = TB ? 40 : (BN + 4);    // TB: [n][k]; NN: [k][n]
    constexpr int ASZ  = BM * ASTR;
    constexpr int BSZ  = TB ? (BN * 40) : (32 * (BN + 4));
    constexpr int NAV  = BM * 8 / 256;
    constexpr int NBV  = TB ? (BN * 8 / 256) : (8 * BN / 256);

    __shared__ float As[2 * ASZ];
    __shared__ float Bs[2 * BSZ];

    const int tid  = threadIdx.x;
    const int wid  = tid >> 5;
    const int lane = tid & 31;
    const int g    = lane >> 2;
    const int tg   = lane & 3;
    const int wm   = (wid / WGN) * WM;
    const int wn   = (wid % WGN) * WN;

    const float* B    = B0;
    const float* bias = bias0;
    float*       C    = C0;
    long long zb = 0, zh = 0;
    if (QKV) {
        int z = blockIdx.z;
        if (z == 1) { B = B1p; bias = bias1p; C = C1p; }
        else if (z == 2) { B = B2p; bias = bias2p; C = C2p; }
    } else {
        int z = blockIdx.z;
        zb = z / HH; zh = z % HH;
    }

    const float* Ab = A + zb * sA1 + zh * sA2 + (size_t)blockIdx.y * BM * lda;
    const float* Bb = B + zb * sB1 + zh * sB2 +
                      (TB ? (size_t)blockIdx.x * BN * ldb : (size_t)blockIdx.x * BN);
    float* Cb = C + zb * sC1 + zh * sC2 +
                (size_t)blockIdx.y * BM * ldc + (size_t)blockIdx.x * BN;

    const uint32_t sA_base = (uint32_t)__cvta_generic_to_shared(As);
    const uint32_t sB_base = (uint32_t)__cvta_generic_to_shared(Bs);

    auto issue = [&](int k0, int st) {
        uint32_t abuf = sA_base + st * ASZ * 4;
#pragma unroll
        for (int i = 0; i < NAV; i++) {
            int idx = tid + i * 256;
            int m = idx >> 3, cv = idx & 7;
            cp16(abuf + (m * ASTR + cv * 4) * 4,
                 Ab + (size_t)m * lda + k0 + cv * 4);
        }
        uint32_t bbuf = sB_base + st * BSZ * 4;
#pragma unroll
        for (int i = 0; i < NBV; i++) {
            int idx = tid + i * 256;
            if (TB) {
                int n = idx >> 3, cv = idx & 7;
                cp16(bbuf + (n * BSTR + cv * 4) * 4,
                     Bb + (size_t)n * ldb + k0 + cv * 4);
            } else {
                int r = idx / (BN / 4), cv = idx % (BN / 4);
                cp16(bbuf + (r * BSTR + cv * 4) * 4,
                     Bb + (size_t)(k0 + r) * ldb + cv * 4);
            }
        }
        cp_commit();
    };

    float c[MI][NJ][4];
#pragma unroll
    for (int mi = 0; mi < MI; mi++)
#pragma unroll
        for (int j = 0; j < NJ; j++)
#pragma unroll
            for (int r = 0; r < 4; r++) c[mi][j][r] = 0.f;

    const int nK = K / 32;
    issue(0, 0);

    for (int kc = 0; kc < nK; kc++) {
        const int st = kc & 1;
        if (kc + 1 < nK) {
            issue((kc + 1) * 32, st ^ 1);
            cp_wait<1>();
        } else {
            cp_wait<0>();
        }
        __syncthreads();

        const float* Ac = As + st * ASZ;
        const float* Bc = Bs + st * BSZ;
#pragma unroll
        for (int kk = 0; kk < 4; kk++) {
            const int ks = kk * 8;
            uint32_t af[MI][4], bf[NJ][2];
#pragma unroll
            for (int mi = 0; mi < MI; mi++) {
                int m = wm + mi * 16 + g;
                float2 p0 = *(const float2*)&Ac[m * ASTR + ks + 2 * tg];
                float2 p1 = *(const float2*)&Ac[(m + 8) * ASTR + ks + 2 * tg];
                af[mi][0] = __float_as_uint(p0.x);
                af[mi][1] = __float_as_uint(p1.x);
                af[mi][2] = __float_as_uint(p0.y);
                af[mi][3] = __float_as_uint(p1.y);
            }
#pragma unroll
            for (int j = 0; j < NJ; j++) {
                int n = wn + j * 8 + g;
                if (TB) {
                    float2 q = *(const float2*)&Bc[n * BSTR + ks + 2 * tg];
                    bf[j][0] = __float_as_uint(q.x);
                    bf[j][1] = __float_as_uint(q.y);
                } else {
                    bf[j][0] = __float_as_uint(Bc[(ks + 2 * tg)     * BSTR + n]);
                    bf[j][1] = __float_as_uint(Bc[(ks + 2 * tg + 1) * BSTR + n]);
                }
            }
#pragma unroll
            for (int mi = 0; mi < MI; mi++)
#pragma unroll
                for (int j = 0; j < NJ; j++) mma8(c[mi][j], af[mi], bf[j]);
        }
        __syncthreads();
    }

    // epilogue
#pragma unroll
    for (int mi = 0; mi < MI; mi++) {
        int r0 = wm + mi * 16 + g;
#pragma unroll
        for (int j = 0; j < NJ; j++) {
            int col = wn + j * 8 + tg * 2;
            float2 bb = make_float2(0.f, 0.f);
            if (bias) bb = *(const float2*)(bias + (size_t)blockIdx.x * BN + col);
            float v0 = c[mi][j][0] * alpha + bb.x;
            float v1 = c[mi][j][1] * alpha + bb.y;
            float v2 = c[mi][j][2] * alpha + bb.x;
            float v3 = c[mi][j][3] * alpha + bb.y;
            if (relu) {
                v0 = fmaxf(v0, 0.f); v1 = fmaxf(v1, 0.f);
                v2 = fmaxf(v2, 0.f); v3 = fmaxf(v3, 0.f);
            }
            if (rnd) { v0 = rtf(v0); v1 = rtf(v1); v2 = rtf(v2); v3 = rtf(v3); }
            *(float2*)(Cb + (size_t)r0 * ldc + col)       = make_float2(v0, v1);
            *(float2*)(Cb + (size_t)(r0 + 8) * ldc + col) = make_float2(v2, v3);
        }
    }
}

// ---------------- scores: single-shot K=64, 128x128 tile ---------------------
__global__ void __launch_bounds__(256, 2) scores_k64(
    const float* __restrict__ Q, const float* __restrict__ Km, float* __restrict__ attn)
{
    constexpr int STR = 72;   // 64 + 8 -> conflict-free LDS.64 / cp.async
    __shared__ float As[128 * STR];
    __shared__ float Bs[128 * STR];

    const int tid  = threadIdx.x;
    const int wid  = tid >> 5;
    const int lane = tid & 31;
    const int g    = lane >> 2;
    const int tg   = lane & 3;
    const int wm   = (wid >> 2) * 64;   // 2 warp rows
    const int wn   = (wid & 3) * 32;    // 4 warp cols

    const int z = blockIdx.z;
    const int b = z / HH, h = z % HH;
    const size_t base = (size_t)b * SS * DD + (size_t)h * DK;
    const int row0 = blockIdx.y * 128;
    const int col0 = blockIdx.x * 128;

    const uint32_t sA = (uint32_t)__cvta_generic_to_shared(As);
    const uint32_t sB = (uint32_t)__cvta_generic_to_shared(Bs);

#pragma unroll
    for (int i = 0; i < 8; i++) {
        int idx = tid + i * 256;
        int m = idx >> 4, cv = idx & 15;
        cp16(sA + (m * STR + cv * 4) * 4, Q  + base + (size_t)(row0 + m) * DD + cv * 4);
        cp16(sB + (m * STR + cv * 4) * 4, Km + base + (size_t)(col0 + m) * DD + cv * 4);
    }
    cp_commit();
    cp_wait<0>();
    __syncthreads();

    float c[4][4][4];
#pragma unroll
    for (int mi = 0; mi < 4; mi++)
#pragma unroll
        for (int j = 0; j < 4; j++)
#pragma unroll
            for (int r = 0; r < 4; r++) c[mi][j][r] = 0.f;

#pragma unroll
    for (int kk = 0; kk < 8; kk++) {
        const int ks = kk * 8;
        uint32_t af[4][4], bf[4][2];
#pragma unroll
        for (int mi = 0; mi < 4; mi++) {
            int m = wm + mi * 16 + g;
            float2 p0 = *(const float2*)&As[m * STR + ks + 2 * tg];
            float2 p1 = *(const float2*)&As[(m + 8) * STR + ks + 2 * tg];
            af[mi][0] = __float_as_uint(p0.x);
            af[mi][1] = __float_as_uint(p1.x);
            af[mi][2] = __float_as_uint(p0.y);
            af[mi][3] = __float_as_uint(p1.y);
        }
#pragma unroll
        for (int j = 0; j < 4; j++) {
            int n = wn + j * 8 + g;
            float2 q = *(const float2*)&Bs[n * STR + ks + 2 * tg];
            bf[j][0] = __float_as_uint(q.x);
            bf[j][1] = __float_as_uint(q.y);
        }
#pragma unroll
        for (int mi = 0; mi < 4; mi++)
#pragma unroll
            for (int j = 0; j < 4; j++) mma8(c[mi][j], af[mi], bf[j]);
    }

    float* out = attn + (size_t)z * SS * SS;
#pragma unroll
    for (int mi = 0; mi < 4; mi++) {
        int r0 = row0 + wm + mi * 16 + g;
#pragma unroll
        for (int j = 0; j < 4; j++) {
            int col = col0 + wn + j * 8 + tg * 2;
            *(float2*)(out + (size_t)r0 * SS + col) =
                make_float2(c[mi][j][0] * 0.125f, c[mi][j][1] * 0.125f);
            *(float2*)(out + (size_t)(r0 + 8) * SS + col) =
                make_float2(c[mi][j][2] * 0.125f, c[mi][j][3] * 0.125f);
        }
    }
}

// ---------------- softmax, in place, rounds output to tf32 --------------------
__global__ void softmax_kernel(float* __restrict__ attn)
{
    size_t row = blockIdx.x;
    float4* p4 = (float4*)(attn + row * SS);
    int t = threadIdx.x;
    __shared__ float red[256];

    float4 v0 = p4[t], v1 = p4[t + 256];
    float m = fmaxf(fmaxf(fmaxf(v0.x, v0.y), fmaxf(v0.z, v0.w)),
                    fmaxf(fmaxf(v1.x, v1.y), fmaxf(v1.z, v1.w)));
    red[t] = m; __syncthreads();
    for (int s = 128; s > 0; s >>= 1) { if (t < s) red[t] = fmaxf(red[t], red[t + s]); __syncthreads(); }
    m = red[0]; __syncthreads();

    v0.x = __expf(v0.x - m); v0.y = __expf(v0.y - m); v0.z = __expf(v0.z - m); v0.w = __expf(v0.w - m);
    v1.x = __expf(v1.x - m); v1.y = __expf(v1.y - m); v1.z = __expf(v1.z - m); v1.w = __expf(v1.w - m);
    float sum = v0.x + v0.y + v0.z + v0.w + v1.x + v1.y + v1.z + v1.w;
    red[t] = sum; __syncthreads();
    for (int s = 128; s > 0; s >>= 1) { if (t < s) red[t] += red[t + s]; __syncthreads(); }
    float inv = 1.0f / red[0];

    v0.x = rtf(v0.x * inv); v0.y = rtf(v0.y * inv); v0.z = rtf(v0.z * inv); v0.w = rtf(v0.w * inv);
    v1.x = rtf(v1.x * inv); v1.y = rtf(v1.y * inv); v1.z = rtf(v1.z * inv); v1.w = rtf(v1.w * inv);
    p4[t] = v0; p4[t + 256] = v1;
}

// ---------------- residual + layernorm, one block per row ---------------------
__global__ void add_ln_kernel(const float* __restrict__ x, const float* __restrict__ y,
                              const float* __restrict__ g, const float* __restrict__ be,
                              float* __restrict__ out, int rnd)
{
    size_t row = blockIdx.x;
    const float* px = x + row * DD;
    const float* py = y + row * DD;
    float* po = out + row * DD;
    int t = threadIdx.x;
    __shared__ float red[256];

    float a0 = px[t]       + py[t];
    float a1 = px[t + 256] + py[t + 256];
    float a2 = px[t + 512] + py[t + 512];

    red[t] = a0 + a1 + a2; __syncthreads();
    for (int s = 128; s > 0; s >>= 1) { if (t < s) red[t] += red[t + s]; __syncthreads(); }
    float mean = red[0] * (1.0f / DD); __syncthreads();

    float d0 = a0 - mean, d1 = a1 - mean, d2 = a2 - mean;
    red[t] = d0 * d0 + d1 * d1 + d2 * d2; __syncthreads();
    for (int s = 128; s > 0; s >>= 1) { if (t < s) red[t] += red[t + s]; __syncthreads(); }
    float rstd = rsqrtf(red[0] * (1.0f / DD) + 1e-5f);

    float o0 = d0 * rstd * g[t]       + be[t];
    float o1 = d1 * rstd * g[t + 256] + be[t + 256];
    float o2 = d2 * rstd * g[t + 512] + be[t + 512];
    if (rnd) { o0 = rtf(o0); o1 = rtf(o1); o2 = rtf(o2); }
    po[t] = o0; po[t + 256] = o1; po[t + 512] = o2;
}

// ---------------- launcher ----------------------------------------------------
extern "C" void kernel_launch(void* const* d_in, const int* in_sizes, int n_in,
                              void* d_out, int out_size)
{
    const float* x   = (const float*)d_in[0];
    const float* Wq  = (const float*)d_in[1];
    const float* bq  = (const float*)d_in[2];
    const float* Wk  = (const float*)d_in[3];
    const float* bk  = (const float*)d_in[4];
    const float* Wv  = (const float*)d_in[5];
    const float* bv  = (const float*)d_in[6];
    const float* Wo  = (const float*)d_in[7];
    const float* bo  = (const float*)d_in[8];
    const float* W1  = (const float*)d_in[9];
    const float* b1  = (const float*)d_in[10];
    const float* W2  = (const float*)d_in[11];
    const float* b2  = (const float*)d_in[12];
    const float* g1  = (const float*)d_in[13];
    const float* be1 = (const float*)d_in[14];
    const float* g2  = (const float*)d_in[15];
    const float* be2 = (const float*)d_in[16];

    float* out  = (float*)d_out;                 // x2: [2,2048,768]
    float* attn = out + X2_ELEMS;                // attn_weights: [2,12,2048,2048]

    float *Qp, *Kp, *Vp, *Cp, *X1p, *T2p, *FFp;
    float *xr, *Wqr, *Wkr, *Wvr, *Wor, *W1r, *W2r;
    cudaGetSymbolAddress((void**)&Qp,  g_Q);
    cudaGetSymbolAddress((void**)&Kp,  g_K);
    cudaGetSymbolAddress((void**)&Vp,  g_V);
    cudaGetSymbolAddress((void**)&Cp,  g_ctx);
    cudaGetSymbolAddress((void**)&X1p, g_x1);
    cudaGetSymbolAddress((void**)&T2p, g_t2);
    cudaGetSymbolAddress((void**)&FFp, g_ff);
    cudaGetSymbolAddress((void**)&xr,  g_xr);
    cudaGetSymbolAddress((void**)&Wqr, g_Wqr);
    cudaGetSymbolAddress((void**)&Wkr, g_Wkr);
    cudaGetSymbolAddress((void**)&Wvr, g_Wvr);
    cudaGetSymbolAddress((void**)&Wor, g_Wor);
    cudaGetSymbolAddress((void**)&W1r, g_W1r);
    cudaGetSymbolAddress((void**)&W2r, g_W2r);

    const long long Z0 = 0;

    // pre-round all GEMM inputs to tf32 (RNA) once
    auto rnd_launch = [&](const float* in, float* o, size_t n) {
        int n4 = (int)(n / 4);
        round_kernel<<<(n4 + 255) / 256, 256>>>((const float4*)in, (float4*)o, n4);
    };
    rnd_launch(x,  xr,  (size_t)MM * DD);
    rnd_launch(Wq, Wqr, (size_t)DD * DD);
    rnd_launch(Wk, Wkr, (size_t)DD * DD);
    rnd_launch(Wv, Wvr, (size_t)DD * DD);
    rnd_launch(Wo, Wor, (size_t)DD * DD);
    rnd_launch(W1, W1r, (size_t)DD * DFF);
    rnd_launch(W2, W2r, (size_t)DFF * DD);

    // merged Q/K/V projections (z selects weight/bias/output), outputs rounded
    gemm_tf32<128,128,64,32,false,true><<<dim3(DD/128, MM/128, 3), 256>>>(
        xr, Wqr, bq, Qp, Wkr, bk, Kp, Wvr, bv, Vp,
        DD, DD, DD, DD, Z0,Z0,Z0,Z0,Z0,Z0, 1.f, 0, 1);

    // scores = Q @ K^T / 8 -> output attn region (single-shot K=64)
    scores_k64<<<dim3(SS/128, SS/128, BB*HH), 256>>>(Qp, Kp, attn);

    // softmax in place, rounds attn to tf32 on write
    softmax_kernel<<<BB*HH*SS, 256>>>(attn);

    // ctx = attn @ V (per head, N=64), output rounded
    gemm_tf32<128,64,32,32,false,false><<<dim3(1, SS/128, BB*HH), 256>>>(
        attn, Vp, nullptr, Cp, nullptr, nullptr, nullptr, nullptr, nullptr, nullptr,
        SS, SS, DD, DD,
        (long long)HH*SS*SS, (long long)SS*SS,
        (long long)SS*DD, (long long)DK,
        (long long)SS*DD, (long long)DK, 1.f, 0, 1);

    // attn_out = ctx @ Wo + bo (fp32 out)
    gemm_tf32<128,128,64,32,false,false><<<dim3(DD/128, MM/128, 1), 256>>>(
        Cp, Wor, bo, T2p, nullptr, nullptr, nullptr, nullptr, nullptr, nullptr,
        DD, DD, DD, DD, Z0,Z0,Z0,Z0,Z0,Z0, 1.f, 0, 0);

    // x1 = LN(x + attn_out), rounded (feeds FFN1)
    add_ln_kernel<<<MM, 256>>>(x, T2p, g1, be1, X1p, 1);

    // ff = relu(x1 @ W1 + b1) rounded; ff2 = ff @ W2 + b2 fp32
    gemm_tf32<128,128,64,32,false,false><<<dim3(DFF/128, MM/128, 1), 256>>>(
        X1p, W1r, b1, FFp, nullptr, nullptr, nullptr, nullptr, nullptr, nullptr,
        DD, DD, DFF, DFF, Z0,Z0,Z0,Z0,Z0,Z0, 1.f, 1, 1);
    gemm_tf32<128,128,64,32,false,false><<<dim3(DD/128, MM/128, 1), 256>>>(
        FFp, W2r, b2, T2p, nullptr, nullptr, nullptr, nullptr, nullptr, nullptr,
        DFF, DFF, DD, DD, Z0,Z0,Z0,Z0,Z0,Z0, 1.f, 0, 0);

    // x2 = LN(x1 + ff2) -> output (fp32)
    add_ln_kernel<<<MM, 256>>>(X1p, T2p, g2, be2, out, 0);
}